// round 4
// baseline (speedup 1.0000x reference)
#include <cuda_runtime.h>
#include <cuda_bf16.h>
#include <cstdint>

#define NN 8192
#define CF 256          // H * OUT_F
#define NHEADS 4

// ---------------- scratch (device globals: allocation-free) ----------------
__device__ float          g_support[(size_t)NN * CF];     // fp32 support
__device__ __nv_bfloat16  g_support_bf[(size_t)NN * CF];  // bf16 copy for attention streaming
__device__ float g_f1[NHEADS * NN], g_a[NHEADS * NN], g_a5[NHEADS * NN];
__device__ float g_f2[NHEADS * NN], g_b[NHEADS * NN], g_b5[NHEADS * NN];

// ---------------- SGEMM: C[m][n] = sum_k A[m][k] * B(k,n) ------------------
// mode 0: write g_support (+ bf16 copy). mode 1: C = gemm + bias1[col] + bias2[col]
// transB=0: B is [K, 256] row-major.  transB=1: B is [256, K], use B[n][k].
__global__ __launch_bounds__(256) void sgemm_kernel(
    const float* __restrict__ A, const float* __restrict__ B,
    float* __restrict__ C, const float* __restrict__ bias1,
    const float* __restrict__ bias2, int K, int transB, int mode)
{
    __shared__ float As[16][68];
    __shared__ float Bs[16][68];
    int tid = threadIdx.x;
    int tx = tid & 15, ty = tid >> 4;
    int m0 = blockIdx.y * 64, n0 = blockIdx.x * 64;
    float acc[4][4] = {};

    for (int kb = 0; kb < K; kb += 16) {
        {   // stage A tile [64 x 16] -> As[k][m]
            int m = tid >> 2, kq = tid & 3;
            float4 a4 = *(const float4*)(A + (size_t)(m0 + m) * K + kb + kq * 4);
            As[kq * 4 + 0][m] = a4.x; As[kq * 4 + 1][m] = a4.y;
            As[kq * 4 + 2][m] = a4.z; As[kq * 4 + 3][m] = a4.w;
        }
        if (!transB) {
            int k = tid >> 4, nq = tid & 15;
            *(float4*)&Bs[k][nq * 4] =
                *(const float4*)(B + (size_t)(kb + k) * CF + n0 + nq * 4);
        } else {
            int n = tid >> 2, kq = tid & 3;
            float4 b4 = *(const float4*)(B + (size_t)(n0 + n) * K + kb + kq * 4);
            Bs[kq * 4 + 0][n] = b4.x; Bs[kq * 4 + 1][n] = b4.y;
            Bs[kq * 4 + 2][n] = b4.z; Bs[kq * 4 + 3][n] = b4.w;
        }
        __syncthreads();
        #pragma unroll
        for (int k = 0; k < 16; ++k) {
            float4 ra = *(const float4*)&As[k][ty * 4];
            float4 rb = *(const float4*)&Bs[k][tx * 4];
            acc[0][0] += ra.x * rb.x; acc[0][1] += ra.x * rb.y;
            acc[0][2] += ra.x * rb.z; acc[0][3] += ra.x * rb.w;
            acc[1][0] += ra.y * rb.x; acc[1][1] += ra.y * rb.y;
            acc[1][2] += ra.y * rb.z; acc[1][3] += ra.y * rb.w;
            acc[2][0] += ra.z * rb.x; acc[2][1] += ra.z * rb.y;
            acc[2][2] += ra.z * rb.z; acc[2][3] += ra.z * rb.w;
            acc[3][0] += ra.w * rb.x; acc[3][1] += ra.w * rb.y;
            acc[3][2] += ra.w * rb.z; acc[3][3] += ra.w * rb.w;
        }
        __syncthreads();
    }

    #pragma unroll
    for (int ii = 0; ii < 4; ++ii) {
        int row = m0 + ty * 4 + ii;
        #pragma unroll
        for (int jj = 0; jj < 4; ++jj) {
            int col = n0 + tx * 4 + jj;
            float v = acc[ii][jj];
            if (mode == 0) {
                g_support[(size_t)row * CF + col] = v;
                g_support_bf[(size_t)row * CF + col] = __float2bfloat16(v);
            } else {
                C[(size_t)row * CF + col] = v + bias1[col] + bias2[col];
            }
        }
    }
}

// ------------- per-node head scalars: f1, f2 and their exponentials ---------
__global__ __launch_bounds__(256) void stats_kernel(
    const float* __restrict__ wu, const float* __restrict__ wv)
{
    int t = blockIdx.x * blockDim.x + threadIdx.x;   // 0 .. 32767
    int n = t >> 2, h = t & 3;
    const float* srow = g_support + (size_t)n * CF + h * 64;
    float s1 = 0.f, s2 = 0.f;
    #pragma unroll 8
    for (int o = 0; o < 64; ++o) {
        float sv = srow[o];
        s1 += sv * wu[h * 64 + o];
        s2 += sv * wv[h * 64 + o];
    }
    int idx = h * NN + n;
    g_f1[idx] = s1;
    g_a [idx] = __expf(s1);
    g_a5[idx] = __expf(0.2f * s1);
    g_f2[idx] = s2;
    g_b [idx] = __expf(s2);
    g_b5[idx] = __expf(0.2f * s2);
}

// -------------------------- sparse attention -------------------------------
// Block: 32 rows (8 warps x 4 rows). Lane owns output cols [lane*8, lane*8+8)
// -> exactly one head per lane (h = lane>>3). Streams j in tiles of 32.
__global__ __launch_bounds__(256) void attn_kernel(
    const float* __restrict__ adj, float* __restrict__ out)
{
    __shared__ float sS[32][256];                 // 32 KB, fp32-expanded support tile
    __shared__ float sf1[4][32], sa[4][32], sa5[4][32];
    __shared__ float sf2[4][32], sb[4][32], sb5[4][32];

    int tid  = threadIdx.x;
    int warp = tid >> 5, lane = tid & 31;
    int i0 = blockIdx.x * 32;
    int h  = lane >> 3;
    int ii_base = warp * 4;

    if (tid < 128) {
        int hh = tid >> 5, ii = tid & 31;
        sf2[hh][ii] = g_f2[hh * NN + i0 + ii];
        sb [hh][ii] = g_b [hh * NN + i0 + ii];
        sb5[hh][ii] = g_b5[hh * NN + i0 + ii];
    }
    __syncthreads();

    float f2r[4], br[4], b5r[4];
    #pragma unroll
    for (int r = 0; r < 4; ++r) {
        f2r[r] = sf2[h][ii_base + r];
        br [r] = sb [h][ii_base + r];
        b5r[r] = sb5[h][ii_base + r];
    }

    float acc[4][8];
    float den[4];
    #pragma unroll
    for (int r = 0; r < 4; ++r) {
        den[r] = 0.f;
        #pragma unroll
        for (int k = 0; k < 8; ++k) acc[r][k] = 0.f;
    }

    for (int jt = 0; jt < NN / 32; ++jt) {
        int j0 = jt * 32;
        __syncthreads();
        // stage support tile (bf16 -> fp32): 32 rows x 256 cols = 1024 uint4
        const uint4* src = (const uint4*)(g_support_bf + (size_t)j0 * CF);
        #pragma unroll
        for (int q = 0; q < 4; ++q) {
            int idx = tid + q * 256;          // 1024 uint4 total (16 KB)
            uint4 v = src[idx];
            int r = idx >> 5, c8 = (idx & 31) << 3;
            float4 lo, hi;
            lo.x = __uint_as_float(v.x << 16); lo.y = __uint_as_float(v.x & 0xffff0000u);
            lo.z = __uint_as_float(v.y << 16); lo.w = __uint_as_float(v.y & 0xffff0000u);
            hi.x = __uint_as_float(v.z << 16); hi.y = __uint_as_float(v.z & 0xffff0000u);
            hi.z = __uint_as_float(v.w << 16); hi.w = __uint_as_float(v.w & 0xffff0000u);
            *(float4*)&sS[r][c8]     = lo;
            *(float4*)&sS[r][c8 + 4] = hi;
        }
        if (tid < 128) {
            int hh = tid >> 5, jj = tid & 31;
            sf1[hh][jj] = g_f1[hh * NN + j0 + jj];
            sa [hh][jj] = g_a [hh * NN + j0 + jj];
            sa5[hh][jj] = g_a5[hh * NN + j0 + jj];
        }
        __syncthreads();

        #pragma unroll
        for (int rr = 0; rr < 4; ++rr) {
            int i = i0 + ii_base + rr;
            float av = adj[(size_t)i * NN + j0 + lane];
            unsigned mask = __ballot_sync(0xffffffffu, av != 0.0f);
            while (mask) {
                int j = __ffs(mask) - 1;
                mask &= mask - 1;
                float f1v = sf1[h][j];
                float e = (f1v + f2r[rr] > 0.0f) ? sa[h][j] * br[rr]
                                                 : sa5[h][j] * b5r[rr];
                den[rr] += e;
                const float4* sp = (const float4*)&sS[j][lane << 3];
                float4 v0 = sp[0], v1 = sp[1];
                acc[rr][0] += e * v0.x; acc[rr][1] += e * v0.y;
                acc[rr][2] += e * v0.z; acc[rr][3] += e * v0.w;
                acc[rr][4] += e * v1.x; acc[rr][5] += e * v1.y;
                acc[rr][6] += e * v1.z; acc[rr][7] += e * v1.w;
            }
        }
    }

    // epilogue: out += attn_out (out already holds proj + biases)
    #pragma unroll
    for (int rr = 0; rr < 4; ++rr) {
        int i = i0 + ii_base + rr;
        float inv = 1.0f / den[rr];
        float* po = out + (size_t)i * CF + (lane << 3);
        float4 o0 = *(float4*)po;
        float4 o1 = *(float4*)(po + 4);
        o0.x += acc[rr][0] * inv; o0.y += acc[rr][1] * inv;
        o0.z += acc[rr][2] * inv; o0.w += acc[rr][3] * inv;
        o1.x += acc[rr][4] * inv; o1.y += acc[rr][5] * inv;
        o1.z += acc[rr][6] * inv; o1.w += acc[rr][7] * inv;
        *(float4*)po       = o0;
        *(float4*)(po + 4) = o1;
    }
}

// ------------------------------- launch ------------------------------------
extern "C" void kernel_launch(void* const* d_in, const int* in_sizes, int n_in,
                              void* d_out, int out_size)
{
    const float* inputs = (const float*)d_in[0];
    const float* adj    = (const float*)d_in[1];
    const float* weight = (const float*)d_in[2];
    const float* wu     = (const float*)d_in[3];
    const float* wv     = (const float*)d_in[4];
    const float* bias   = (const float*)d_in[5];
    const float* projw  = (const float*)d_in[6];
    const float* projb  = (const float*)d_in[7];
    float* out = (float*)d_out;

    dim3 gemm_grid(CF / 64, NN / 64);   // (4, 128)

    // support = inputs @ weight  (also writes bf16 copy)
    sgemm_kernel<<<gemm_grid, 256>>>(inputs, weight, nullptr, nullptr, nullptr,
                                     256, 0, 0);
    // per-node head scalars + exponentials
    stats_kernel<<<NN * NHEADS / 256, 256>>>(wu, wv);
    // out = inputs @ proj_w.T + bias + proj_b
    sgemm_kernel<<<gemm_grid, 256>>>(inputs, projw, out, bias, projb,
                                     256, 1, 1);
    // out += sparse-softmax attention output
    attn_kernel<<<NN / 32, 256>>>(adj, out);
}

// round 5
// speedup vs baseline: 3.1694x; 3.1694x over previous
#include <cuda_runtime.h>
#include <cuda_bf16.h>
#include <cstdint>

#define NN 8192
#define CF 256          // H * OUT_F
#define NHEADS 4
#define CHUNKS 8
#define JTILE 32
#define JCHUNK (NN / CHUNKS)          // 1024
#define NT (JCHUNK / JTILE)           // 32 tiles per chunk
#define RPB 64                        // i-rows per block
#define ATHREADS 512

// ---------------- scratch (device globals: allocation-free) ----------------
__device__ float  g_support[(size_t)NN * CF];       // fp32 support (for stats)
__device__ float  g_support_perm[(size_t)NN * CF];  // column-permuted fp32 support
__device__ float4 g_statJ[NN * NHEADS];             // {f1, e^f1, e^.2f1, 0} per (j,h)
__device__ float4 g_statI[NN * NHEADS];             // {f2, e^f2, e^.2f2, 0} per (i,h)
__device__ float  g_pnum[(size_t)CHUNKS * NN * CF]; // partial numerators
__device__ float  g_pden[(size_t)CHUNKS * NN * NHEADS];

#define CP16(saddr, gptr) \
    asm volatile("cp.async.cg.shared.global [%0], [%1], 16;" \
                 :: "r"(saddr), "l"(gptr))
#define CP_COMMIT() asm volatile("cp.async.commit_group;")
#define CP_WAIT1()  asm volatile("cp.async.wait_group 1;" ::: "memory")

// ---------------- SGEMM: C[m][n] = sum_k A[m][k] * B(k,n) ------------------
// mode 0: write g_support + permuted copy. mode 1: C = gemm + bias1 + bias2
__global__ __launch_bounds__(256) void sgemm_kernel(
    const float* __restrict__ A, const float* __restrict__ B,
    float* __restrict__ C, const float* __restrict__ bias1,
    const float* __restrict__ bias2, int K, int transB, int mode)
{
    __shared__ float As[16][68];
    __shared__ float Bs[16][68];
    int tid = threadIdx.x;
    int tx = tid & 15, ty = tid >> 4;
    int m0 = blockIdx.y * 64, n0 = blockIdx.x * 64;
    float acc[4][4] = {};

    for (int kb = 0; kb < K; kb += 16) {
        {
            int m = tid >> 2, kq = tid & 3;
            float4 a4 = *(const float4*)(A + (size_t)(m0 + m) * K + kb + kq * 4);
            As[kq * 4 + 0][m] = a4.x; As[kq * 4 + 1][m] = a4.y;
            As[kq * 4 + 2][m] = a4.z; As[kq * 4 + 3][m] = a4.w;
        }
        if (!transB) {
            int k = tid >> 4, nq = tid & 15;
            *(float4*)&Bs[k][nq * 4] =
                *(const float4*)(B + (size_t)(kb + k) * CF + n0 + nq * 4);
        } else {
            int n = tid >> 2, kq = tid & 3;
            float4 b4 = *(const float4*)(B + (size_t)(n0 + n) * K + kb + kq * 4);
            Bs[kq * 4 + 0][n] = b4.x; Bs[kq * 4 + 1][n] = b4.y;
            Bs[kq * 4 + 2][n] = b4.z; Bs[kq * 4 + 3][n] = b4.w;
        }
        __syncthreads();
        #pragma unroll
        for (int k = 0; k < 16; ++k) {
            float4 ra = *(const float4*)&As[k][ty * 4];
            float4 rb = *(const float4*)&Bs[k][tx * 4];
            acc[0][0] += ra.x * rb.x; acc[0][1] += ra.x * rb.y;
            acc[0][2] += ra.x * rb.z; acc[0][3] += ra.x * rb.w;
            acc[1][0] += ra.y * rb.x; acc[1][1] += ra.y * rb.y;
            acc[1][2] += ra.y * rb.z; acc[1][3] += ra.y * rb.w;
            acc[2][0] += ra.z * rb.x; acc[2][1] += ra.z * rb.y;
            acc[2][2] += ra.z * rb.z; acc[2][3] += ra.z * rb.w;
            acc[3][0] += ra.w * rb.x; acc[3][1] += ra.w * rb.y;
            acc[3][2] += ra.w * rb.z; acc[3][3] += ra.w * rb.w;
        }
        __syncthreads();
    }

    #pragma unroll
    for (int ii = 0; ii < 4; ++ii) {
        int row = m0 + ty * 4 + ii;
        #pragma unroll
        for (int jj = 0; jj < 4; ++jj) {
            int col = n0 + tx * 4 + jj;
            float v = acc[ii][jj];
            if (mode == 0) {
                g_support[(size_t)row * CF + col] = v;
                // permuted position: lane (col>>3) owns 8 cols; first 4 at
                // lane*4 in [0,128), last 4 at 128 + lane*4.
                int g = col >> 3, half = (col >> 2) & 1, q = col & 3;
                int p = half * 128 + g * 4 + q;
                g_support_perm[(size_t)row * CF + p] = v;
            } else {
                C[(size_t)row * CF + col] = v + bias1[col] + bias2[col];
            }
        }
    }
}

// ------------- per-node head scalars: f1, f2 and their exponentials ---------
__global__ __launch_bounds__(256) void stats_kernel(
    const float* __restrict__ wu, const float* __restrict__ wv)
{
    int t = blockIdx.x * blockDim.x + threadIdx.x;   // 0 .. 32767
    int n = t >> 2, h = t & 3;
    const float* srow = g_support + (size_t)n * CF + h * 64;
    float s1 = 0.f, s2 = 0.f;
    #pragma unroll 8
    for (int o = 0; o < 64; ++o) {
        float sv = srow[o];
        s1 += sv * wu[h * 64 + o];
        s2 += sv * wv[h * 64 + o];
    }
    g_statJ[n * NHEADS + h] = make_float4(s1, __expf(s1), __expf(0.2f * s1), 0.f);
    g_statI[n * NHEADS + h] = make_float4(s2, __expf(s2), __expf(0.2f * s2), 0.f);
}

// -------------------------- sparse attention (partial) ---------------------
// grid (128, 8): blockIdx.x = i-block (64 rows), blockIdx.y = j-chunk (1024 j)
// block 512 thr = 16 warps; warp w owns rows w*4..w*4+3; lane owns cols lane*8..+7.
__global__ __launch_bounds__(ATHREADS, 1) void attn_partial(
    const float* __restrict__ adj)
{
    extern __shared__ char smraw[];
    float*  sS    = (float*)smraw;                          // [2][32][256] fp32 (perm)
    float4* sstat = (float4*)(smraw + 2 * JTILE * CF * 4);  // [2][32][4]

    int tid = threadIdx.x, warp = tid >> 5, lane = tid & 31;
    int i0 = blockIdx.x * RPB;
    int chunk = blockIdx.y;
    int j0 = chunk * JCHUNK;
    int h = lane >> 3;
    int ibase = i0 + warp * 4;

    auto issue_tile = [&](int t, int b) {
        const char* src = (const char*)(g_support_perm + (size_t)(j0 + t * JTILE) * CF);
        unsigned dstS = (unsigned)__cvta_generic_to_shared(sS + (size_t)b * JTILE * CF);
        #pragma unroll
        for (int s = 0; s < 4; ++s) {
            int cid = tid + s * ATHREADS;          // 0..2047 chunks of 16B
            CP16(dstS + cid * 16, src + cid * 16);
        }
        if (tid < JTILE * NHEADS) {
            const char* sj = (const char*)(g_statJ + (size_t)(j0 + t * JTILE) * NHEADS);
            unsigned dstT = (unsigned)__cvta_generic_to_shared(sstat + b * JTILE * NHEADS);
            CP16(dstT + tid * 16, sj + tid * 16);
        }
    };

    float f2r[4], br[4], b5r[4];
    #pragma unroll
    for (int rr = 0; rr < 4; ++rr) {
        float4 si = g_statI[(size_t)(ibase + rr) * NHEADS + h];
        f2r[rr] = si.x; br[rr] = si.y; b5r[rr] = si.z;
    }

    unsigned long long accp[4][4] = {};   // packed f32x2 accumulators
    float den[4] = {0.f, 0.f, 0.f, 0.f};

    float av[4];
    #pragma unroll
    for (int rr = 0; rr < 4; ++rr)
        av[rr] = adj[(size_t)(ibase + rr) * NN + j0 + lane];

    issue_tile(0, 0); CP_COMMIT();
    issue_tile(1, 1); CP_COMMIT();

    for (int jt = 0; jt < NT; ++jt) {
        int b = jt & 1;
        CP_WAIT1();
        __syncthreads();

        unsigned m[4];
        #pragma unroll
        for (int rr = 0; rr < 4; ++rr)
            m[rr] = __ballot_sync(0xffffffffu, av[rr] != 0.0f);

        if (jt + 1 < NT) {
            #pragma unroll
            for (int rr = 0; rr < 4; ++rr)
                av[rr] = adj[(size_t)(ibase + rr) * NN + j0 + (jt + 1) * JTILE + lane];
        }

        const float*  tile = sS + (size_t)b * JTILE * CF;
        const float4* stt  = sstat + b * JTILE * NHEADS;

        #pragma unroll
        for (int rr = 0; rr < 4; ++rr) {
            unsigned mask = m[rr];
            while (mask) {
                int j = __ffs(mask) - 1;
                mask &= mask - 1;
                float4 st = stt[j * NHEADS + h];            // {f1, e^f1, e^.2f1}
                float f = st.x + f2r[rr];
                float e = (f > 0.0f) ? st.y * br[rr] : st.z * b5r[rr];
                den[rr] += e;
                unsigned long long e2;
                asm("mov.b64 %0, {%1, %1};" : "=l"(e2) : "f"(e));
                const ulonglong2* sp =
                    (const ulonglong2*)(tile + (size_t)j * CF) + lane; // 16B @ lane*16
                ulonglong2 w0 = sp[0];       // orig cols lane*8 .. +3
                ulonglong2 w1 = sp[32];      // +512B: cols lane*8+4 .. +7
                asm("fma.rn.f32x2 %0, %1, %2, %0;" : "+l"(accp[rr][0]) : "l"(w0.x), "l"(e2));
                asm("fma.rn.f32x2 %0, %1, %2, %0;" : "+l"(accp[rr][1]) : "l"(w0.y), "l"(e2));
                asm("fma.rn.f32x2 %0, %1, %2, %0;" : "+l"(accp[rr][2]) : "l"(w1.x), "l"(e2));
                asm("fma.rn.f32x2 %0, %1, %2, %0;" : "+l"(accp[rr][3]) : "l"(w1.y), "l"(e2));
            }
        }

        __syncthreads();                     // all warps done reading buf b
        if (jt + 2 < NT) issue_tile(jt + 2, b);
        CP_COMMIT();
    }

    // write partials
    #pragma unroll
    for (int rr = 0; rr < 4; ++rr) {
        int i = ibase + rr;
        float o[8];
        #pragma unroll
        for (int k = 0; k < 4; ++k) {
            unsigned lo, hi;
            asm("mov.b64 {%0, %1}, %2;" : "=r"(lo), "=r"(hi) : "l"(accp[rr][k]));
            o[k * 2]     = __uint_as_float(lo);
            o[k * 2 + 1] = __uint_as_float(hi);
        }
        float* pn = g_pnum + ((size_t)chunk * NN + i) * CF + (lane << 3);
        *(float4*)pn       = make_float4(o[0], o[1], o[2], o[3]);
        *(float4*)(pn + 4) = make_float4(o[4], o[5], o[6], o[7]);
        if ((lane & 7) == 0)
            g_pden[((size_t)chunk * NN + i) * NHEADS + h] = den[rr];
    }
}

// -------------------- combine partials: out += num/den ---------------------
__global__ __launch_bounds__(256) void combine_kernel(float* __restrict__ out)
{
    int i = blockIdx.x;
    int c = threadIdx.x;
    int h = c >> 6;
    float s = 0.f, d = 0.f;
    #pragma unroll
    for (int k = 0; k < CHUNKS; ++k) {
        s += g_pnum[((size_t)k * NN + i) * CF + c];
        d += g_pden[((size_t)k * NN + i) * NHEADS + h];
    }
    out[(size_t)i * CF + c] += s / d;
}

// ------------------------------- launch ------------------------------------
extern "C" void kernel_launch(void* const* d_in, const int* in_sizes, int n_in,
                              void* d_out, int out_size)
{
    const float* inputs = (const float*)d_in[0];
    const float* adj    = (const float*)d_in[1];
    const float* weight = (const float*)d_in[2];
    const float* wu     = (const float*)d_in[3];
    const float* wv     = (const float*)d_in[4];
    const float* bias   = (const float*)d_in[5];
    const float* projw  = (const float*)d_in[6];
    const float* projb  = (const float*)d_in[7];
    float* out = (float*)d_out;

    const int ASMEM = 2 * JTILE * CF * 4 + 2 * JTILE * NHEADS * 16;  // 69632
    cudaFuncSetAttribute(attn_partial,
                         cudaFuncAttributeMaxDynamicSharedMemorySize, ASMEM);

    dim3 gemm_grid(CF / 64, NN / 64);   // (4, 128)

    // support = inputs @ weight (also writes permuted copy)
    sgemm_kernel<<<gemm_grid, 256>>>(inputs, weight, nullptr, nullptr, nullptr,
                                     256, 0, 0);
    // per-node head scalars + exponentials
    stats_kernel<<<NN * NHEADS / 256, 256>>>(wu, wv);
    // out = inputs @ proj_w.T + bias + proj_b
    sgemm_kernel<<<gemm_grid, 256>>>(inputs, projw, out, bias, projb,
                                     256, 1, 1);
    // partial attention over j-chunks
    attn_partial<<<dim3(NN / RPB, CHUNKS), ATHREADS, ASMEM>>>(adj);
    // out += num/den
    combine_kernel<<<NN, 256>>>(out);
}

// round 6
// speedup vs baseline: 3.3096x; 1.0442x over previous
#include <cuda_runtime.h>
#include <cuda_bf16.h>
#include <cstdint>

#define NN 8192
#define CF 256          // H * OUT_F
#define NHEADS 4
#define CHUNKS 8
#define JTILE 32
#define JCHUNK (NN / CHUNKS)          // 1024
#define NT (JCHUNK / JTILE)           // 32 tiles per chunk
#define RPB 64                        // i-rows per block
#define ATHREADS 512

// ---------------- scratch (device globals: allocation-free) ----------------
__device__ float  g_support[(size_t)NN * CF];       // fp32 support (for stats)
__device__ float  g_support_perm[(size_t)NN * CF];  // column-permuted fp32 support
__device__ float2 g_statJ[NN * NHEADS];             // {e^f1, e^.2f1} per (j,h)
__device__ float2 g_statI[NN * NHEADS];             // {e^f2, e^.2f2} per (i,h)
__device__ float  g_pnum[(size_t)CHUNKS * NN * CF]; // partial numerators
__device__ float  g_pden[(size_t)CHUNKS * NN * NHEADS];

#define CP16(saddr, gptr) \
    asm volatile("cp.async.cg.shared.global [%0], [%1], 16;" \
                 :: "r"(saddr), "l"(gptr))
#define CP_COMMIT() asm volatile("cp.async.commit_group;")
#define CP_WAIT1()  asm volatile("cp.async.wait_group 1;" ::: "memory")

// ---------------- SGEMM: C[m][n] = sum_k A[m][k] * B(k,n) ------------------
// mode 0: write g_support + permuted copy. mode 1: C = gemm + bias1 + bias2
__global__ __launch_bounds__(256) void sgemm_kernel(
    const float* __restrict__ A, const float* __restrict__ B,
    float* __restrict__ C, const float* __restrict__ bias1,
    const float* __restrict__ bias2, int K, int transB, int mode)
{
    __shared__ float As[16][68];
    __shared__ float Bs[16][68];
    int tid = threadIdx.x;
    int tx = tid & 15, ty = tid >> 4;
    int m0 = blockIdx.y * 64, n0 = blockIdx.x * 64;
    float acc[4][4] = {};

    for (int kb = 0; kb < K; kb += 16) {
        {
            int m = tid >> 2, kq = tid & 3;
            float4 a4 = *(const float4*)(A + (size_t)(m0 + m) * K + kb + kq * 4);
            As[kq * 4 + 0][m] = a4.x; As[kq * 4 + 1][m] = a4.y;
            As[kq * 4 + 2][m] = a4.z; As[kq * 4 + 3][m] = a4.w;
        }
        if (!transB) {
            int k = tid >> 4, nq = tid & 15;
            *(float4*)&Bs[k][nq * 4] =
                *(const float4*)(B + (size_t)(kb + k) * CF + n0 + nq * 4);
        } else {
            int n = tid >> 2, kq = tid & 3;
            float4 b4 = *(const float4*)(B + (size_t)(n0 + n) * K + kb + kq * 4);
            Bs[kq * 4 + 0][n] = b4.x; Bs[kq * 4 + 1][n] = b4.y;
            Bs[kq * 4 + 2][n] = b4.z; Bs[kq * 4 + 3][n] = b4.w;
        }
        __syncthreads();
        #pragma unroll
        for (int k = 0; k < 16; ++k) {
            float4 ra = *(const float4*)&As[k][ty * 4];
            float4 rb = *(const float4*)&Bs[k][tx * 4];
            acc[0][0] += ra.x * rb.x; acc[0][1] += ra.x * rb.y;
            acc[0][2] += ra.x * rb.z; acc[0][3] += ra.x * rb.w;
            acc[1][0] += ra.y * rb.x; acc[1][1] += ra.y * rb.y;
            acc[1][2] += ra.y * rb.z; acc[1][3] += ra.y * rb.w;
            acc[2][0] += ra.z * rb.x; acc[2][1] += ra.z * rb.y;
            acc[2][2] += ra.z * rb.z; acc[2][3] += ra.z * rb.w;
            acc[3][0] += ra.w * rb.x; acc[3][1] += ra.w * rb.y;
            acc[3][2] += ra.w * rb.z; acc[3][3] += ra.w * rb.w;
        }
        __syncthreads();
    }

    #pragma unroll
    for (int ii = 0; ii < 4; ++ii) {
        int row = m0 + ty * 4 + ii;
        #pragma unroll
        for (int jj = 0; jj < 4; ++jj) {
            int col = n0 + tx * 4 + jj;
            float v = acc[ii][jj];
            if (mode == 0) {
                g_support[(size_t)row * CF + col] = v;
                // permuted: lane (col>>3) owns 8 cols; first 4 at lane*4 in
                // [0,128), last 4 at 128 + lane*4.
                int g = col >> 3, half = (col >> 2) & 1, q = col & 3;
                int p = half * 128 + g * 4 + q;
                g_support_perm[(size_t)row * CF + p] = v;
            } else {
                C[(size_t)row * CF + col] = v + bias1[col] + bias2[col];
            }
        }
    }
}

// ------------- per-node head scalars: exponentials only ---------------------
__global__ __launch_bounds__(256) void stats_kernel(
    const float* __restrict__ wu, const float* __restrict__ wv)
{
    int t = blockIdx.x * blockDim.x + threadIdx.x;   // 0 .. 32767
    int n = t >> 2, h = t & 3;
    const float* srow = g_support + (size_t)n * CF + h * 64;
    float s1 = 0.f, s2 = 0.f;
    #pragma unroll 8
    for (int o = 0; o < 64; ++o) {
        float sv = srow[o];
        s1 += sv * wu[h * 64 + o];
        s2 += sv * wv[h * 64 + o];
    }
    g_statJ[n * NHEADS + h] = make_float2(__expf(s1), __expf(0.2f * s1));
    g_statI[n * NHEADS + h] = make_float2(__expf(s2), __expf(0.2f * s2));
}

// -------------------------- sparse attention (partial) ---------------------
// grid (128, 8): blockIdx.x = i-block (64 rows), blockIdx.y = j-chunk (1024 j)
// block 512 thr = 16 warps; warp w owns rows w*4..w*4+3; lane owns cols lane*8..+7.
__global__ __launch_bounds__(ATHREADS, 2) void attn_partial(
    const float* __restrict__ adj)
{
    extern __shared__ char smraw[];
    float*  sS    = (float*)smraw;                          // [2][32][256] fp32 (perm)
    float2* sstat = (float2*)(smraw + 2 * JTILE * CF * 4);  // [2][32][4]

    int tid = threadIdx.x, warp = tid >> 5, lane = tid & 31;
    int i0 = blockIdx.x * RPB;
    int chunk = blockIdx.y;
    int j0 = chunk * JCHUNK;
    int h = lane >> 3;
    int ibase = i0 + warp * 4;

    auto issue_tile = [&](int t, int b) {
        const char* src = (const char*)(g_support_perm + (size_t)(j0 + t * JTILE) * CF);
        unsigned dstS = (unsigned)__cvta_generic_to_shared(sS + (size_t)b * JTILE * CF);
        #pragma unroll
        for (int s = 0; s < 4; ++s) {
            int cid = tid + s * ATHREADS;          // 0..2047 chunks of 16B
            CP16(dstS + cid * 16, src + cid * 16);
        }
        if (tid < JTILE * NHEADS / 2) {            // 1024 B of stats = 64 x 16B
            const char* sj = (const char*)(g_statJ + (size_t)(j0 + t * JTILE) * NHEADS);
            unsigned dstT = (unsigned)__cvta_generic_to_shared(sstat + b * JTILE * NHEADS);
            CP16(dstT + tid * 16, sj + tid * 16);
        }
    };

    float br[4], b5r[4];
    #pragma unroll
    for (int rr = 0; rr < 4; ++rr) {
        float2 si = g_statI[(size_t)(ibase + rr) * NHEADS + h];
        br[rr] = si.x; b5r[rr] = si.y;
    }

    unsigned long long accp[4][4] = {};   // packed f32x2 accumulators
    float den[4] = {0.f, 0.f, 0.f, 0.f};

    float av[4];
    #pragma unroll
    for (int rr = 0; rr < 4; ++rr)
        av[rr] = adj[(size_t)(ibase + rr) * NN + j0 + lane];

    issue_tile(0, 0); CP_COMMIT();
    issue_tile(1, 1); CP_COMMIT();

    for (int jt = 0; jt < NT; ++jt) {
        int b = jt & 1;
        CP_WAIT1();
        __syncthreads();

        unsigned m[4];
        #pragma unroll
        for (int rr = 0; rr < 4; ++rr)
            m[rr] = __ballot_sync(0xffffffffu, av[rr] != 0.0f);

        if (jt + 1 < NT) {
            #pragma unroll
            for (int rr = 0; rr < 4; ++rr)
                av[rr] = adj[(size_t)(ibase + rr) * NN + j0 + (jt + 1) * JTILE + lane];
        }

        const float*  tile = sS + (size_t)b * JTILE * CF;
        const float2* stt  = sstat + b * JTILE * NHEADS;

        #pragma unroll
        for (int rr = 0; rr < 4; ++rr) {
            unsigned mask = m[rr];
            while (mask) {
                int j = __ffs(mask) - 1;
                mask &= mask - 1;
                float2 st = stt[j * NHEADS + h];            // {e^f1, e^.2f1}
                // exp(leaky_relu(f1+f2)) == max(e^f1 e^f2, e^.2f1 e^.2f2)
                float e = fmaxf(st.x * br[rr], st.y * b5r[rr]);
                den[rr] += e;
                unsigned long long e2;
                asm("mov.b64 %0, {%1, %1};" : "=l"(e2) : "f"(e));
                const ulonglong2* sp =
                    (const ulonglong2*)(tile + (size_t)j * CF) + lane; // 16B @ lane*16
                ulonglong2 w0 = sp[0];       // orig cols lane*8 .. +3
                ulonglong2 w1 = sp[32];      // +512B: cols lane*8+4 .. +7
                asm("fma.rn.f32x2 %0, %1, %2, %0;" : "+l"(accp[rr][0]) : "l"(w0.x), "l"(e2));
                asm("fma.rn.f32x2 %0, %1, %2, %0;" : "+l"(accp[rr][1]) : "l"(w0.y), "l"(e2));
                asm("fma.rn.f32x2 %0, %1, %2, %0;" : "+l"(accp[rr][2]) : "l"(w1.x), "l"(e2));
                asm("fma.rn.f32x2 %0, %1, %2, %0;" : "+l"(accp[rr][3]) : "l"(w1.y), "l"(e2));
            }
        }

        __syncthreads();                     // all warps done reading buf b
        if (jt + 2 < NT) issue_tile(jt + 2, b);
        CP_COMMIT();
    }

    // write partials
    #pragma unroll
    for (int rr = 0; rr < 4; ++rr) {
        int i = ibase + rr;
        float o[8];
        #pragma unroll
        for (int k = 0; k < 4; ++k) {
            unsigned lo, hi;
            asm("mov.b64 {%0, %1}, %2;" : "=r"(lo), "=r"(hi) : "l"(accp[rr][k]));
            o[k * 2]     = __uint_as_float(lo);
            o[k * 2 + 1] = __uint_as_float(hi);
        }
        float* pn = g_pnum + ((size_t)chunk * NN + i) * CF + (lane << 3);
        *(float4*)pn       = make_float4(o[0], o[1], o[2], o[3]);
        *(float4*)(pn + 4) = make_float4(o[4], o[5], o[6], o[7]);
        if ((lane & 7) == 0)
            g_pden[((size_t)chunk * NN + i) * NHEADS + h] = den[rr];
    }
}

// -------------------- combine partials: out += num/den ---------------------
__global__ __launch_bounds__(256) void combine_kernel(float* __restrict__ out)
{
    int i = blockIdx.x;
    int c = threadIdx.x;
    int h = c >> 6;
    float s = 0.f, d = 0.f;
    #pragma unroll
    for (int k = 0; k < CHUNKS; ++k) {
        s += g_pnum[((size_t)k * NN + i) * CF + c];
        d += g_pden[((size_t)k * NN + i) * NHEADS + h];
    }
    out[(size_t)i * CF + c] += s / d;
}

// ------------------------------- launch ------------------------------------
extern "C" void kernel_launch(void* const* d_in, const int* in_sizes, int n_in,
                              void* d_out, int out_size)
{
    const float* inputs = (const float*)d_in[0];
    const float* adj    = (const float*)d_in[1];
    const float* weight = (const float*)d_in[2];
    const float* wu     = (const float*)d_in[3];
    const float* wv     = (const float*)d_in[4];
    const float* bias   = (const float*)d_in[5];
    const float* projw  = (const float*)d_in[6];
    const float* projb  = (const float*)d_in[7];
    float* out = (float*)d_out;

    const int ASMEM = 2 * JTILE * CF * 4 + 2 * JTILE * NHEADS * 8;  // 67584
    cudaFuncSetAttribute(attn_partial,
                         cudaFuncAttributeMaxDynamicSharedMemorySize, ASMEM);

    dim3 gemm_grid(CF / 64, NN / 64);   // (4, 128)

    // support = inputs @ weight (also writes permuted copy)
    sgemm_kernel<<<gemm_grid, 256>>>(inputs, weight, nullptr, nullptr, nullptr,
                                     256, 0, 0);
    // per-node head scalars + exponentials
    stats_kernel<<<NN * NHEADS / 256, 256>>>(wu, wv);
    // out = inputs @ proj_w.T + bias + proj_b
    sgemm_kernel<<<gemm_grid, 256>>>(inputs, projw, out, bias, projb,
                                     256, 1, 1);
    // partial attention over j-chunks
    attn_partial<<<dim3(NN / RPB, CHUNKS), ATHREADS, ASMEM>>>(adj);
    // out += num/den
    combine_kernel<<<NN, 256>>>(out);
}